// round 2
// baseline (speedup 1.0000x reference)
#include <cuda_runtime.h>
#include <cstdint>
#include <math.h>

typedef unsigned long long ULL;

// ---------------------------------------------------------------------------
// Problem constants (fixed by the reference)
// ---------------------------------------------------------------------------
#define BATCH     16
#define LFULL     (1 << 21)      // 2097152
#define KW        256            // CQT kernel width
#define PADK      128
#define TFRAMES   4097
#define NOCT      7
#define NB12      12

// Scratch for downsampled signals x1..x6, layout [batch][len] per stage.
// Total = 16 * (2^20 + 2^19 + ... + 2^15) = 33,030,144 floats (~132 MB)
static __device__ __align__(16) float g_scratch[33030144];

// Start offset (floats) of stage s signal within g_scratch (stage 0 = original x,
// lives in the harness input buffer, offset unused).
__constant__ size_t c_off[7] = {
    0,          // stage 0 (unused, reads original x)
    0,          // stage 1
    16777216,   // stage 2
    25165824,   // stage 3
    29360128,   // stage 4
    31457280,   // stage 5
    32505856    // stage 6
};

// ---------------------------------------------------------------------------
// f32x2 helpers (Blackwell packed fp32)
// ---------------------------------------------------------------------------
__device__ __forceinline__ void fma2(ULL& d, ULL a, ULL b) {
    asm("fma.rn.f32x2 %0, %1, %2, %0;" : "+l"(d) : "l"(a), "l"(b));
}
__device__ __forceinline__ ULL pack2(float x, float y) {
    ULL r; asm("mov.b64 %0, {%1, %2};" : "=l"(r) : "f"(x), "f"(y)); return r;
}
__device__ __forceinline__ float2 unpack2(ULL v) {
    float2 f; asm("mov.b64 {%0, %1}, %2;" : "=f"(f.x), "=f"(f.y) : "l"(v)); return f;
}

// ---------------------------------------------------------------------------
// Downsample-by-2 with 256-tap FIR, zero padding (127,127).
// Polyphase:  y[t] = sum_j o[t-64+j]*h[2j] + e[t-63+j]*h[2j+1]
// with e[m]=x[2m], o[m]=x[2m+1]. Packed pair sp[m] = {o[m], e[m+1]}.
// Block: 128 threads x 8 consecutive outputs = 1024 outputs/block.
// Stage s reads stage-(s) signal, writes stage-(s+1) signal (both resolved
// device-side from g_scratch; stage 0 reads the harness input x).
// ---------------------------------------------------------------------------
#define DS_TPB   128
#define DS_OPB   1024
#define DS_WIN   (DS_OPB + 128)          // 1152 window pairs
#define DS_WPAD  (DS_WIN + DS_WIN / 8)   // 1296 (bank-conflict pad)

__global__ void __launch_bounds__(DS_TPB)
ds_kernel(const float* __restrict__ x_orig, int stage,
          const float* __restrict__ lp)
{
    __shared__ float2 sp[DS_WPAD];
    __shared__ float2 sc[128];

    const int tid   = threadIdx.x;
    const int batch = blockIdx.y;
    const int t0    = blockIdx.x * DS_OPB;
    const int Lin   = LFULL >> stage;
    const int Lout  = Lin >> 1;

    const float* xb = (stage == 0)
        ? (x_orig + ((size_t)batch << 21))
        : (g_scratch + c_off[stage] + (size_t)batch * Lin);
    float* yb = g_scratch + c_off[stage + 1] + (size_t)batch * Lout;

    if (tid < 128) sc[tid] = ((const float2*)lp)[tid];

    for (int idx = tid; idx < DS_WIN; idx += DS_TPB) {
        int m = t0 - 64 + idx;
        float o = 0.f, e = 0.f;
        int a = 2 * m + 1;
        if (a >= 0 && a < Lin) o = xb[a];
        int b = 2 * m + 2;
        if (b >= 0 && b < Lin) e = xb[b];
        sp[idx + (idx >> 3)] = make_float2(o, e);
    }
    __syncthreads();

    const ULL* spw = (const ULL*)sp;
    const ULL* scw = (const ULL*)sc;

    const int base = tid * 8;
    ULL acc[8], w[8];
#pragma unroll
    for (int r = 0; r < 8; r++) acc[r] = 0ULL;
#pragma unroll
    for (int r = 0; r < 8; r++) { int i = base + r; w[r] = spw[i + (i >> 3)]; }

#pragma unroll
    for (int j = 0; j < 128; j++) {
        ULL c = scw[j];
#pragma unroll
        for (int r = 0; r < 8; r++) fma2(acc[r], w[r], c);
#pragma unroll
        for (int r = 0; r < 7; r++) w[r] = w[r + 1];
        int i = base + j + 8;
        w[7] = spw[i + (i >> 3)];
    }

    float res[8];
#pragma unroll
    for (int r = 0; r < 8; r++) { float2 f = unpack2(acc[r]); res[r] = f.x + f.y; }

    float* yp = yb + t0 + base;
    *(float4*)(yp)     = make_float4(res[0], res[1], res[2], res[3]);
    *(float4*)(yp + 4) = make_float4(res[4], res[5], res[6], res[7]);
}

// ---------------------------------------------------------------------------
// CQT conv + magnitude, one launch for all 7 stages.
// Warp layout: 4 frame-groups (g) x 8 tap-lanes (l); each lane handles 2 frames.
// Warp covers 8 frames; block (8 warps) covers 64 frames.
// Coefs staged in smem as {kr,ki} pairs: stride 14 ULL per tap (conflict-free).
// ---------------------------------------------------------------------------
__global__ void __launch_bounds__(256)
cqt_kernel(const float* __restrict__ x,
           const float* __restrict__ kr, const float* __restrict__ ki,
           const float* __restrict__ lengths, float* __restrict__ out)
{
    __shared__ ulonglong2 ct[256 * 7];   // per tap: 7 x ulonglong2 = 14 ULL = 12 pairs + pad
    __shared__ float sl[12];

    const int stage = blockIdx.y;
    const int batch = blockIdx.z;
    const int Ls    = LFULL >> stage;
    const int hop   = 512 >> stage;
    const int boff  = 12 * (6 - stage);
    const int tid   = threadIdx.x;

    float* ctf = (float*)ct;
    for (int idx = tid; idx < 12 * 256; idx += 256) {
        int k = idx >> 8, tap = idx & 255;
        ctf[tap * 28 + 2 * k]     = kr[idx];
        ctf[tap * 28 + 2 * k + 1] = ki[idx];
    }
    if (tid < 12) sl[tid] = sqrtf(lengths[boff + tid]);
    __syncthreads();

    const float* sig = (stage == 0)
        ? (x + ((size_t)batch << 21))
        : (g_scratch + c_off[stage] + (size_t)batch * Ls);

    const int wid  = tid >> 5;
    const int lane = tid & 31;
    const int g    = lane >> 3;
    const int l    = lane & 7;

    const int f0  = blockIdx.x * 64 + wid * 8 + 2 * g;
    const int f1  = f0 + 1;
    const int t0c = min(f0, TFRAMES - 1);
    const int t1c = min(f1, TFRAMES - 1);
    const int b0  = t0c * hop - PADK;
    const int b1  = t1c * hop - PADK;

    ULL a0[12], a1[12];
#pragma unroll
    for (int k = 0; k < 12; k++) { a0[k] = 0ULL; a1[k] = 0ULL; }

#pragma unroll
    for (int m = 0; m < 32; m++) {
        const int tap = l + (m << 3);
        int u0 = b0 + tap;
        u0 = (u0 < 0) ? -u0 : u0;
        if (u0 >= Ls) u0 = 2 * Ls - 2 - u0;
        int u1 = b1 + tap;
        u1 = (u1 < 0) ? -u1 : u1;
        if (u1 >= Ls) u1 = 2 * Ls - 2 - u1;

        const float v0 = __ldg(sig + u0);
        const float v1 = __ldg(sig + u1);
        const ULL p0 = pack2(v0, v0);
        const ULL p1 = pack2(v1, v1);

        const ulonglong2* cp = ct + tap * 7;
#pragma unroll
        for (int kk = 0; kk < 6; kk++) {
            ulonglong2 c = cp[kk];
            fma2(a0[2 * kk],     p0, c.x);
            fma2(a0[2 * kk + 1], p0, c.y);
            fma2(a1[2 * kk],     p1, c.x);
            fma2(a1[2 * kk + 1], p1, c.y);
        }
    }

    // Reduce over the 8 tap-lanes within each frame-group, fuse magnitude, write.
#pragma unroll
    for (int k = 0; k < 12; k++) {
        float2 r0 = unpack2(a0[k]);
        float2 r1 = unpack2(a1[k]);
#pragma unroll
        for (int s = 1; s < 8; s <<= 1) {
            r0.x += __shfl_xor_sync(0xffffffffu, r0.x, s);
            r0.y += __shfl_xor_sync(0xffffffffu, r0.y, s);
            r1.x += __shfl_xor_sync(0xffffffffu, r1.x, s);
            r1.y += __shfl_xor_sync(0xffffffffu, r1.y, s);
        }
        if ((k & 7) == l) {
            const float s_k = sl[k];
            const size_t rowbase = ((size_t)batch * 84 + boff + k) * (size_t)TFRAMES;
            if (f0 < TFRAMES) {
                float m0 = sqrtf(fmaf(r0.x, r0.x, fmaf(r0.y, r0.y, 1e-8f))) * s_k;
                out[rowbase + f0] = m0;
            }
            if (f1 < TFRAMES) {
                float m1 = sqrtf(fmaf(r1.x, r1.x, fmaf(r1.y, r1.y, 1e-8f))) * s_k;
                out[rowbase + f1] = m1;
            }
        }
    }
}

// ---------------------------------------------------------------------------
// Launch: pure kernel launches only (graph-capture hardened).
// ---------------------------------------------------------------------------
extern "C" void kernel_launch(void* const* d_in, const int* in_sizes, int n_in,
                              void* d_out, int out_size)
{
    const float* x    = (const float*)d_in[0];
    const float* kr   = (const float*)d_in[1];
    const float* ki   = (const float*)d_in[2];
    const float* lp   = (const float*)d_in[3];
    const float* lens = (const float*)d_in[4];
    float* out        = (float*)d_out;

    // Downsample chain: stage s -> stage s+1 (s = 0..5)
    for (int s = 0; s < NOCT - 1; s++) {
        int Lout = (LFULL >> s) >> 1;
        dim3 grid(Lout / DS_OPB, BATCH);
        ds_kernel<<<grid, DS_TPB>>>(x, s, lp);
    }

    // All 7 octaves of CQT + magnitude in one launch.
    dim3 cgrid((TFRAMES + 63) / 64, NOCT, BATCH);
    cqt_kernel<<<cgrid, 256>>>(x, kr, ki, lens, out);
}

// round 3
// speedup vs baseline: 1.0628x; 1.0628x over previous
#include <cuda_runtime.h>
#include <cstdint>
#include <math.h>

typedef unsigned long long ULL;

// ---------------------------------------------------------------------------
// Problem constants (fixed by the reference)
// ---------------------------------------------------------------------------
#define BATCH     16
#define LFULL     (1 << 21)      // 2097152
#define PADK      128
#define TFRAMES   4097
#define NOCT      7

// Scratch for downsampled signals x1..x6, layout [batch][len] per stage.
static __device__ __align__(16) float g_scratch[33030144];

__constant__ size_t c_off[7] = {
    0,          // stage 0 (reads original x)
    0,          // stage 1
    16777216,   // stage 2
    25165824,   // stage 3
    29360128,   // stage 4
    31457280,   // stage 5
    32505856    // stage 6
};

// ---------------------------------------------------------------------------
// f32x2 helpers (packed fp32 FMA)
// ---------------------------------------------------------------------------
__device__ __forceinline__ void fma2(ULL& d, ULL a, ULL b) {
    asm("fma.rn.f32x2 %0, %1, %2, %0;" : "+l"(d) : "l"(a), "l"(b));
}
__device__ __forceinline__ ULL pack2(float x, float y) {
    ULL r; asm("mov.b64 %0, {%1, %2};" : "=l"(r) : "f"(x), "f"(y)); return r;
}
__device__ __forceinline__ float2 unpack2(ULL v) {
    float2 f; asm("mov.b64 {%0, %1}, %2;" : "=f"(f.x), "=f"(f.y) : "l"(v)); return f;
}

// ---------------------------------------------------------------------------
// Downsample-by-2, 256-tap FIR, zero padding (127,127).
// Polyphase: y[t] = sum_j {o[t-64+j], e[t-63+j]} . {h[2j], h[2j+1]}
// with e[m]=x[2m], o[m]=x[2m+1]; packed pair sp[m] = {o[m], e[m+1]}.
//
// v2: chunked software pipeline.
//  - 8 outputs/thread, 16-ULL double-buffered window (banks A/B, swap per
//    8-tap chunk -> no register shifting, small loop body (fits L0 I$)).
//  - window refills + coef loads via LDS.128.
//  - smem pad i + (i>>3)*2 : preserves 16B alignment; thread stride becomes
//    10 ULL = 20 words -> 8 threads/phase hit 8 distinct 4-word groups
//    covering all 32 banks (conflict-free LDS.128).
// ---------------------------------------------------------------------------
#define DS_TPB   128
#define DS_OPB   1024
#define DS_WIN   1184                      // 1024 + 128 halo + slack
#define DS_PADI(i) ((i) + (((i) >> 3) << 1))
#define DS_SPSZ  1488                      // > DS_PADI(1183) = 1477

__global__ void __launch_bounds__(DS_TPB)
ds_kernel(const float* __restrict__ x_orig, int stage,
          const float* __restrict__ lp)
{
    __shared__ ULL sp[DS_SPSZ];
    __shared__ __align__(16) ULL sc[128];

    const int tid   = threadIdx.x;
    const int batch = blockIdx.y;
    const int t0    = blockIdx.x * DS_OPB;
    const int Lin   = LFULL >> stage;
    const int Lout  = Lin >> 1;

    const float* xb = (stage == 0)
        ? (x_orig + ((size_t)batch << 21))
        : (g_scratch + c_off[stage] + (size_t)batch * Lin);
    float* yb = g_scratch + c_off[stage + 1] + (size_t)batch * Lout;

    // coefs: sc[j] = {h[2j], h[2j+1]}
    {
        float2 h = ((const float2*)lp)[tid];
        sc[tid] = pack2(h.x, h.y);
    }

    // window pairs into smem (zero-padded edges)
    for (int idx = tid; idx < DS_WIN; idx += DS_TPB) {
        int m = t0 - 64 + idx;
        float o = 0.f, e = 0.f;
        int a = 2 * m + 1;
        if (a >= 0 && a < Lin) o = xb[a];
        int b = 2 * m + 2;
        if (b >= 0 && b < Lin) e = xb[b];
        sp[DS_PADI(idx)] = pack2(o, e);
    }
    __syncthreads();

    const int base = tid * 8;   // first window index for this thread

    ULL acc[8];
#pragma unroll
    for (int r = 0; r < 8; r++) acc[r] = 0ULL;

    ULL A[8], B[8];
    // initial window: A = w[base..base+7], B = w[base+8..base+15]
#pragma unroll
    for (int r = 0; r < 8; r += 2) {
        ulonglong2 v = *(const ulonglong2*)&sp[DS_PADI(base + r)];
        A[r] = v.x; A[r + 1] = v.y;
    }
#pragma unroll
    for (int r = 0; r < 8; r += 2) {
        ulonglong2 v = *(const ulonglong2*)&sp[DS_PADI(base + 8 + r)];
        B[r] = v.x; B[r + 1] = v.y;
    }

#pragma unroll 1
    for (int it = 0; it < 8; it++) {
        const int cbase = it * 16;

        // coefs for chunk 2*it
        ULL c0[8];
#pragma unroll
        for (int j = 0; j < 8; j += 2) {
            ulonglong2 v = *(const ulonglong2*)&sc[cbase + j];
            c0[j] = v.x; c0[j + 1] = v.y;
        }
        // compute chunk 2*it with window (A,B)
#pragma unroll
        for (int q = 0; q < 8; q++) {
#pragma unroll
            for (int r = 0; r < 8; r++) {
                const int w = q + r;
                fma2(acc[r], (w < 8) ? A[w] : B[w - 8], c0[q]);
            }
        }
        // refill A <- w[base + cbase + 16 .. +23]
#pragma unroll
        for (int r = 0; r < 8; r += 2) {
            ulonglong2 v = *(const ulonglong2*)&sp[DS_PADI(base + cbase + 16 + r)];
            A[r] = v.x; A[r + 1] = v.y;
        }

        // coefs for chunk 2*it+1
        ULL c1[8];
#pragma unroll
        for (int j = 0; j < 8; j += 2) {
            ulonglong2 v = *(const ulonglong2*)&sc[cbase + 8 + j];
            c1[j] = v.x; c1[j + 1] = v.y;
        }
        // compute chunk 2*it+1 with window (B,A)
#pragma unroll
        for (int q = 0; q < 8; q++) {
#pragma unroll
            for (int r = 0; r < 8; r++) {
                const int w = q + r;
                fma2(acc[r], (w < 8) ? B[w] : A[w - 8], c1[q]);
            }
        }
        // refill B <- w[base + cbase + 24 .. +31]
#pragma unroll
        for (int r = 0; r < 8; r += 2) {
            ulonglong2 v = *(const ulonglong2*)&sp[DS_PADI(base + cbase + 24 + r)];
            B[r] = v.x; B[r + 1] = v.y;
        }
    }

    float res[8];
#pragma unroll
    for (int r = 0; r < 8; r++) { float2 f = unpack2(acc[r]); res[r] = f.x + f.y; }

    float* yp = yb + t0 + base;
    *(float4*)(yp)     = make_float4(res[0], res[1], res[2], res[3]);
    *(float4*)(yp + 4) = make_float4(res[4], res[5], res[6], res[7]);
}

// ---------------------------------------------------------------------------
// CQT conv + magnitude, one launch for all 7 stages.
// v2: warp = 8 tap-lanes (l) x 4 frame-groups (g); each lane owns 4
// consecutive frames -> warp covers 16 frames, block (8 warps) covers 128.
// Bins processed in 2 passes of 6 (24 ULL accumulators/pass).
// Coef smem: per tap 12 {kr,ki} ULL pairs stored with stride 14 ULL
// (tap-distinct banks, conflict-free LDS.128).
// ---------------------------------------------------------------------------
__global__ void __launch_bounds__(256)
cqt_kernel(const float* __restrict__ x,
           const float* __restrict__ kr, const float* __restrict__ ki,
           const float* __restrict__ lengths, float* __restrict__ out)
{
    __shared__ ulonglong2 ct[256 * 7];
    __shared__ float sl[12];

    const int stage = blockIdx.y;
    const int batch = blockIdx.z;
    const int Ls    = LFULL >> stage;
    const int hop   = 512 >> stage;
    const int boff  = 12 * (6 - stage);
    const int tid   = threadIdx.x;

    float* ctf = (float*)ct;
    for (int idx = tid; idx < 12 * 256; idx += 256) {
        int k = idx >> 8, tap = idx & 255;
        ctf[tap * 28 + 2 * k]     = kr[idx];
        ctf[tap * 28 + 2 * k + 1] = ki[idx];
    }
    if (tid < 12) sl[tid] = sqrtf(lengths[boff + tid]);
    __syncthreads();

    const float* sig = (stage == 0)
        ? (x + ((size_t)batch << 21))
        : (g_scratch + c_off[stage] + (size_t)batch * Ls);

    const int wid  = tid >> 5;
    const int lane = tid & 31;
    const int g    = lane >> 3;
    const int l    = lane & 7;

    const int fbase = blockIdx.x * 128 + wid * 16 + g * 4;

    int b[4];
#pragma unroll
    for (int r = 0; r < 4; r++) {
        int t = min(fbase + r, TFRAMES - 1);
        b[r] = t * hop - PADK;
    }

#pragma unroll 1
    for (int pass = 0; pass < 2; pass++) {
        ULL a0[6], a1[6], a2[6], a3[6];
#pragma unroll
        for (int k = 0; k < 6; k++) { a0[k] = 0; a1[k] = 0; a2[k] = 0; a3[k] = 0; }

#pragma unroll 4
        for (int m = 0; m < 32; m++) {
            const int tap = l + (m << 3);

            int u0 = b[0] + tap; u0 = (u0 < 0) ? -u0 : u0; if (u0 >= Ls) u0 = 2 * Ls - 2 - u0;
            int u1 = b[1] + tap; u1 = (u1 < 0) ? -u1 : u1; if (u1 >= Ls) u1 = 2 * Ls - 2 - u1;
            int u2 = b[2] + tap; u2 = (u2 < 0) ? -u2 : u2; if (u2 >= Ls) u2 = 2 * Ls - 2 - u2;
            int u3 = b[3] + tap; u3 = (u3 < 0) ? -u3 : u3; if (u3 >= Ls) u3 = 2 * Ls - 2 - u3;

            const float v0 = __ldg(sig + u0);
            const float v1 = __ldg(sig + u1);
            const float v2 = __ldg(sig + u2);
            const float v3 = __ldg(sig + u3);
            const ULL p0 = pack2(v0, v0);
            const ULL p1 = pack2(v1, v1);
            const ULL p2 = pack2(v2, v2);
            const ULL p3 = pack2(v3, v3);

            const ulonglong2* cp = ct + tap * 7 + 3 * pass;
#pragma unroll
            for (int j = 0; j < 3; j++) {
                ulonglong2 c = cp[j];
                fma2(a0[2 * j],     p0, c.x);
                fma2(a0[2 * j + 1], p0, c.y);
                fma2(a1[2 * j],     p1, c.x);
                fma2(a1[2 * j + 1], p1, c.y);
                fma2(a2[2 * j],     p2, c.x);
                fma2(a2[2 * j + 1], p2, c.y);
                fma2(a3[2 * j],     p3, c.x);
                fma2(a3[2 * j + 1], p3, c.y);
            }
        }

        // reduce across the 8 tap-lanes (xor 1,2,4 affect only l bits)
#pragma unroll
        for (int k = 0; k < 6; k++) {
            float2 r0 = unpack2(a0[k]);
            float2 r1 = unpack2(a1[k]);
            float2 r2 = unpack2(a2[k]);
            float2 r3 = unpack2(a3[k]);
#pragma unroll
            for (int s = 1; s < 8; s <<= 1) {
                r0.x += __shfl_xor_sync(0xffffffffu, r0.x, s);
                r0.y += __shfl_xor_sync(0xffffffffu, r0.y, s);
                r1.x += __shfl_xor_sync(0xffffffffu, r1.x, s);
                r1.y += __shfl_xor_sync(0xffffffffu, r1.y, s);
                r2.x += __shfl_xor_sync(0xffffffffu, r2.x, s);
                r2.y += __shfl_xor_sync(0xffffffffu, r2.y, s);
                r3.x += __shfl_xor_sync(0xffffffffu, r3.x, s);
                r3.y += __shfl_xor_sync(0xffffffffu, r3.y, s);
            }
            if (l == k) {
                const int bin = 6 * pass + k;
                const float s_k = sl[bin];
                const size_t rowbase =
                    ((size_t)batch * 84 + boff + bin) * (size_t)TFRAMES;
                float m0 = sqrtf(fmaf(r0.x, r0.x, fmaf(r0.y, r0.y, 1e-8f))) * s_k;
                float m1 = sqrtf(fmaf(r1.x, r1.x, fmaf(r1.y, r1.y, 1e-8f))) * s_k;
                float m2 = sqrtf(fmaf(r2.x, r2.x, fmaf(r2.y, r2.y, 1e-8f))) * s_k;
                float m3 = sqrtf(fmaf(r3.x, r3.x, fmaf(r3.y, r3.y, 1e-8f))) * s_k;
                if (fbase + 0 < TFRAMES) out[rowbase + fbase + 0] = m0;
                if (fbase + 1 < TFRAMES) out[rowbase + fbase + 1] = m1;
                if (fbase + 2 < TFRAMES) out[rowbase + fbase + 2] = m2;
                if (fbase + 3 < TFRAMES) out[rowbase + fbase + 3] = m3;
            }
        }
    }
}

// ---------------------------------------------------------------------------
// Launch: pure kernel launches only.
// ---------------------------------------------------------------------------
extern "C" void kernel_launch(void* const* d_in, const int* in_sizes, int n_in,
                              void* d_out, int out_size)
{
    const float* x    = (const float*)d_in[0];
    const float* kr   = (const float*)d_in[1];
    const float* ki   = (const float*)d_in[2];
    const float* lp   = (const float*)d_in[3];
    const float* lens = (const float*)d_in[4];
    float* out        = (float*)d_out;

    for (int s = 0; s < NOCT - 1; s++) {
        int Lout = (LFULL >> s) >> 1;
        dim3 grid(Lout / DS_OPB, BATCH);
        ds_kernel<<<grid, DS_TPB>>>(x, s, lp);
    }

    dim3 cgrid((TFRAMES + 127) / 128, NOCT, BATCH);
    cqt_kernel<<<cgrid, 256>>>(x, kr, ki, lens, out);
}

// round 5
// speedup vs baseline: 1.1829x; 1.1130x over previous
#include <cuda_runtime.h>
#include <cstdint>
#include <math.h>

typedef unsigned long long ULL;

// ---------------------------------------------------------------------------
// Problem constants (fixed by the reference)
// ---------------------------------------------------------------------------
#define BATCH     16
#define LFULL     (1 << 21)      // 2097152
#define PADK      128
#define TFRAMES   4097
#define NOCT      7

// Scratch for downsampled signals x1..x6, layout [batch][len] per stage.
static __device__ __align__(16) float g_scratch[33030144];

__constant__ size_t c_off[7] = {
    0,          // stage 0 (reads original x)
    0,          // stage 1
    16777216,   // stage 2
    25165824,   // stage 3
    29360128,   // stage 4
    31457280,   // stage 5
    32505856    // stage 6
};

// Lowpass coefficients, pre-paired {h[2j], h[2j+1]} as 64-bit words.
// Filled by cudaMemcpyToSymbolAsync (D2D) in kernel_launch.
// Warp-uniform indexing -> LDCU.64 -> uniform-register FFMA2 operand
// (drops RF-bank operand pressure 3 -> 2 -> fma pipe rt 3 -> 2).
__constant__ ULL c_lp[128];

// ---------------------------------------------------------------------------
// f32x2 helpers (packed fp32 FMA)
// ---------------------------------------------------------------------------
__device__ __forceinline__ void fma2(ULL& d, ULL a, ULL b) {
    asm("fma.rn.f32x2 %0, %1, %2, %0;" : "+l"(d) : "l"(a), "l"(b));
}
__device__ __forceinline__ ULL pack2(float x, float y) {
    ULL r; asm("mov.b64 %0, {%1, %2};" : "=l"(r) : "f"(x), "f"(y)); return r;
}
__device__ __forceinline__ float2 unpack2(ULL v) {
    float2 f; asm("mov.b64 {%0, %1}, %2;" : "=f"(f.x), "=f"(f.y) : "l"(v)); return f;
}

// ---------------------------------------------------------------------------
// Downsample-by-2, 256-tap FIR, zero padding (127,127).
// Polyphase: y[t] = sum_j {o[t-64+j], e[t-63+j]} . {h[2j], h[2j+1]}
// with e[m]=x[2m], o[m]=x[2m+1]; packed pair sp[m] = {o[m], e[m+1]}.
//
// Chunked pipeline, coefficients from __constant__ (uniform regs).
//  - 8 outputs/thread, 16-ULL double-buffered window (banks A/B swapped per
//    8-tap chunk; no register shifting, small loop body).
//  - window refills via LDS.128; pad i + (i>>3)*2 keeps 16B alignment and
//    makes the 20-word thread stride cover all 32 banks conflict-free.
//  - coefficients via LDCU.64 (no smem traffic, UR operand).
// ---------------------------------------------------------------------------
#define DS_TPB   128
#define DS_OPB   1024
#define DS_WIN   1184                      // 1024 + 128 halo + slack
#define DS_PADI(i) ((i) + (((i) >> 3) << 1))
#define DS_SPSZ  1488                      // > DS_PADI(1183) = 1477

__global__ void __launch_bounds__(DS_TPB)
ds_kernel(const float* __restrict__ x_orig, int stage)
{
    __shared__ ULL sp[DS_SPSZ];

    const int tid   = threadIdx.x;
    const int batch = blockIdx.y;
    const int t0    = blockIdx.x * DS_OPB;
    const int Lin   = LFULL >> stage;
    const int Lout  = Lin >> 1;

    const float* xb = (stage == 0)
        ? (x_orig + ((size_t)batch << 21))
        : (g_scratch + c_off[stage] + (size_t)batch * Lin);
    float* yb = g_scratch + c_off[stage + 1] + (size_t)batch * Lout;

    // window pairs into smem (zero-padded edges)
    for (int idx = tid; idx < DS_WIN; idx += DS_TPB) {
        int m = t0 - 64 + idx;
        float o = 0.f, e = 0.f;
        int a = 2 * m + 1;
        if (a >= 0 && a < Lin) o = xb[a];
        int b = 2 * m + 2;
        if (b >= 0 && b < Lin) e = xb[b];
        sp[DS_PADI(idx)] = pack2(o, e);
    }
    __syncthreads();

    const int base = tid * 8;   // first window index for this thread

    ULL acc[8];
#pragma unroll
    for (int r = 0; r < 8; r++) acc[r] = 0ULL;

    ULL A[8], B[8];
#pragma unroll
    for (int r = 0; r < 8; r += 2) {
        ulonglong2 v = *(const ulonglong2*)&sp[DS_PADI(base + r)];
        A[r] = v.x; A[r + 1] = v.y;
    }
#pragma unroll
    for (int r = 0; r < 8; r += 2) {
        ulonglong2 v = *(const ulonglong2*)&sp[DS_PADI(base + 8 + r)];
        B[r] = v.x; B[r + 1] = v.y;
    }

#pragma unroll 1
    for (int it = 0; it < 8; it++) {
        const int cbase = it * 16;

        // chunk 2*it with window (A,B); coefs from constant (uniform)
#pragma unroll
        for (int q = 0; q < 8; q++) {
            const ULL c = c_lp[cbase + q];
#pragma unroll
            for (int r = 0; r < 8; r++) {
                const int w = q + r;
                fma2(acc[r], (w < 8) ? A[w] : B[w - 8], c);
            }
        }
        // refill A <- w[base + cbase + 16 .. +23]
#pragma unroll
        for (int r = 0; r < 8; r += 2) {
            ulonglong2 v = *(const ulonglong2*)&sp[DS_PADI(base + cbase + 16 + r)];
            A[r] = v.x; A[r + 1] = v.y;
        }

        // chunk 2*it+1 with window (B,A)
#pragma unroll
        for (int q = 0; q < 8; q++) {
            const ULL c = c_lp[cbase + 8 + q];
#pragma unroll
            for (int r = 0; r < 8; r++) {
                const int w = q + r;
                fma2(acc[r], (w < 8) ? B[w] : A[w - 8], c);
            }
        }
        // refill B <- w[base + cbase + 24 .. +31]
#pragma unroll
        for (int r = 0; r < 8; r += 2) {
            ulonglong2 v = *(const ulonglong2*)&sp[DS_PADI(base + cbase + 24 + r)];
            B[r] = v.x; B[r + 1] = v.y;
        }
    }

    float res[8];
#pragma unroll
    for (int r = 0; r < 8; r++) { float2 f = unpack2(acc[r]); res[r] = f.x + f.y; }

    float* yp = yb + t0 + base;
    *(float4*)(yp)     = make_float4(res[0], res[1], res[2], res[3]);
    *(float4*)(yp + 4) = make_float4(res[4], res[5], res[6], res[7]);
}

// ---------------------------------------------------------------------------
// CQT conv + magnitude, one launch for all 7 stages.
// Warp = 8 tap-lanes (l) x 4 frame-groups (g); each lane owns 4 consecutive
// frames -> warp covers 16 frames, block (8 warps) covers 128.
// Bins in 2 passes of 6 (24 ULL accumulators/pass).
// Coef smem: per tap 12 {kr,ki} ULL pairs, stride 14 ULL (conflict-free).
// ---------------------------------------------------------------------------
__global__ void __launch_bounds__(256)
cqt_kernel(const float* __restrict__ x,
           const float* __restrict__ kr, const float* __restrict__ ki,
           const float* __restrict__ lengths, float* __restrict__ out)
{
    __shared__ ulonglong2 ct[256 * 7];
    __shared__ float sl[12];

    const int stage = blockIdx.y;
    const int batch = blockIdx.z;
    const int Ls    = LFULL >> stage;
    const int hop   = 512 >> stage;
    const int boff  = 12 * (6 - stage);
    const int tid   = threadIdx.x;

    float* ctf = (float*)ct;
    for (int idx = tid; idx < 12 * 256; idx += 256) {
        int k = idx >> 8, tap = idx & 255;
        ctf[tap * 28 + 2 * k]     = kr[idx];
        ctf[tap * 28 + 2 * k + 1] = ki[idx];
    }
    if (tid < 12) sl[tid] = sqrtf(lengths[boff + tid]);
    __syncthreads();

    const float* sig = (stage == 0)
        ? (x + ((size_t)batch << 21))
        : (g_scratch + c_off[stage] + (size_t)batch * Ls);

    const int wid  = tid >> 5;
    const int lane = tid & 31;
    const int g    = lane >> 3;
    const int l    = lane & 7;

    const int fbase = blockIdx.x * 128 + wid * 16 + g * 4;

    int b[4];
#pragma unroll
    for (int r = 0; r < 4; r++) {
        int t = min(fbase + r, TFRAMES - 1);
        b[r] = t * hop - PADK;
    }

#pragma unroll 1
    for (int pass = 0; pass < 2; pass++) {
        ULL a0[6], a1[6], a2[6], a3[6];
#pragma unroll
        for (int k = 0; k < 6; k++) { a0[k] = 0; a1[k] = 0; a2[k] = 0; a3[k] = 0; }

#pragma unroll 4
        for (int m = 0; m < 32; m++) {
            const int tap = l + (m << 3);

            int u0 = b[0] + tap; u0 = (u0 < 0) ? -u0 : u0; if (u0 >= Ls) u0 = 2 * Ls - 2 - u0;
            int u1 = b[1] + tap; u1 = (u1 < 0) ? -u1 : u1; if (u1 >= Ls) u1 = 2 * Ls - 2 - u1;
            int u2 = b[2] + tap; u2 = (u2 < 0) ? -u2 : u2; if (u2 >= Ls) u2 = 2 * Ls - 2 - u2;
            int u3 = b[3] + tap; u3 = (u3 < 0) ? -u3 : u3; if (u3 >= Ls) u3 = 2 * Ls - 2 - u3;

            const float v0 = __ldg(sig + u0);
            const float v1 = __ldg(sig + u1);
            const float v2 = __ldg(sig + u2);
            const float v3 = __ldg(sig + u3);
            const ULL p0 = pack2(v0, v0);
            const ULL p1 = pack2(v1, v1);
            const ULL p2 = pack2(v2, v2);
            const ULL p3 = pack2(v3, v3);

            const ulonglong2* cp = ct + tap * 7 + 3 * pass;
#pragma unroll
            for (int j = 0; j < 3; j++) {
                ulonglong2 c = cp[j];
                fma2(a0[2 * j],     p0, c.x);
                fma2(a0[2 * j + 1], p0, c.y);
                fma2(a1[2 * j],     p1, c.x);
                fma2(a1[2 * j + 1], p1, c.y);
                fma2(a2[2 * j],     p2, c.x);
                fma2(a2[2 * j + 1], p2, c.y);
                fma2(a3[2 * j],     p3, c.x);
                fma2(a3[2 * j + 1], p3, c.y);
            }
        }

        // reduce across the 8 tap-lanes (xor 1,2,4 affect only l bits)
#pragma unroll
        for (int k = 0; k < 6; k++) {
            float2 r0 = unpack2(a0[k]);
            float2 r1 = unpack2(a1[k]);
            float2 r2 = unpack2(a2[k]);
            float2 r3 = unpack2(a3[k]);
#pragma unroll
            for (int s = 1; s < 8; s <<= 1) {
                r0.x += __shfl_xor_sync(0xffffffffu, r0.x, s);
                r0.y += __shfl_xor_sync(0xffffffffu, r0.y, s);
                r1.x += __shfl_xor_sync(0xffffffffu, r1.x, s);
                r1.y += __shfl_xor_sync(0xffffffffu, r1.y, s);
                r2.x += __shfl_xor_sync(0xffffffffu, r2.x, s);
                r2.y += __shfl_xor_sync(0xffffffffu, r2.y, s);
                r3.x += __shfl_xor_sync(0xffffffffu, r3.x, s);
                r3.y += __shfl_xor_sync(0xffffffffu, r3.y, s);
            }
            if (l == k) {
                const int bin = 6 * pass + k;
                const float s_k = sl[bin];
                const size_t rowbase =
                    ((size_t)batch * 84 + boff + bin) * (size_t)TFRAMES;
                float m0 = sqrtf(fmaf(r0.x, r0.x, fmaf(r0.y, r0.y, 1e-8f))) * s_k;
                float m1 = sqrtf(fmaf(r1.x, r1.x, fmaf(r1.y, r1.y, 1e-8f))) * s_k;
                float m2 = sqrtf(fmaf(r2.x, r2.x, fmaf(r2.y, r2.y, 1e-8f))) * s_k;
                float m3 = sqrtf(fmaf(r3.x, r3.x, fmaf(r3.y, r3.y, 1e-8f))) * s_k;
                if (fbase + 0 < TFRAMES) out[rowbase + fbase + 0] = m0;
                if (fbase + 1 < TFRAMES) out[rowbase + fbase + 1] = m1;
                if (fbase + 2 < TFRAMES) out[rowbase + fbase + 2] = m2;
                if (fbase + 3 < TFRAMES) out[rowbase + fbase + 3] = m3;
            }
        }
    }
}

// ---------------------------------------------------------------------------
// Launch: kernel launches + one D2D memcpy-to-symbol (graph-capture legal).
// ---------------------------------------------------------------------------
extern "C" void kernel_launch(void* const* d_in, const int* in_sizes, int n_in,
                              void* d_out, int out_size)
{
    const float* x    = (const float*)d_in[0];
    const float* kr   = (const float*)d_in[1];
    const float* ki   = (const float*)d_in[2];
    const float* lp   = (const float*)d_in[3];
    const float* lens = (const float*)d_in[4];
    float* out        = (float*)d_out;

    // Lowpass coefs -> constant bank, pre-paired {h[2j],h[2j+1]} (raw bytes).
    cudaMemcpyToSymbolAsync(c_lp, lp, 128 * sizeof(ULL), 0,
                            cudaMemcpyDeviceToDevice, 0);

    for (int s = 0; s < NOCT - 1; s++) {
        int Lout = (LFULL >> s) >> 1;
        dim3 grid(Lout / DS_OPB, BATCH);
        ds_kernel<<<grid, DS_TPB>>>(x, s);
    }

    dim3 cgrid((TFRAMES + 127) / 128, NOCT, BATCH);
    cqt_kernel<<<cgrid, 256>>>(x, kr, ki, lens, out);
}